// round 1
// baseline (speedup 1.0000x reference)
#include <cuda_runtime.h>
#include <math.h>
#include <stdint.h>
#include <stddef.h>

// Problem constants
#define TSTEPS 1024
#define BATCH  128
#define INDIM  512
#define HID    512
#define GATES  2048   // 4*HID, gate order: i, f, o, g

// ---------------------------------------------------------------------------
// Device-global scratch (allocation-free kernel_launch requirement)
// ---------------------------------------------------------------------------
// xproj stored TRANSPOSED per timestep: g_xprojT[t][gate][batch]
__device__ float g_xprojT[(size_t)TSTEPS * GATES * BATCH];   // 1 GiB
// hidden state double buffer, stored transposed: [k][b]
__device__ float g_hT[2][HID * BATCH];
// grid barrier state (self-resetting: deterministic across graph replays)
__device__ unsigned g_count;
__device__ unsigned g_gen;

__device__ __forceinline__ void grid_barrier(unsigned nb) {
    __syncthreads();
    if (threadIdx.x == 0) {
        unsigned my = *(volatile unsigned*)&g_gen;
        __threadfence();
        unsigned old = atomicAdd(&g_count, 1u);
        if (old == nb - 1u) {
            atomicExch(&g_count, 0u);
            __threadfence();
            atomicAdd(&g_gen, 1u);
        } else {
            while (*(volatile unsigned*)&g_gen == my) { }
        }
        __threadfence();
    }
    __syncthreads();
}

// ---------------------------------------------------------------------------
// Phase 1: xproj[t][g][b] = sum_k x[t][b][k] * W_ih[g][k] + b_ih[g] + b_hh[g]
// Classic 128x128x8 SGEMM tile, 256 threads, 8x8 per thread (split 4+4),
// register-prefetched global loads. Both operands are K-contiguous (NT GEMM).
// BM=128 == BATCH, so each m-tile is exactly one timestep -> transposed store
// xprojT[t][n][b] is coalesced along b.
// ---------------------------------------------------------------------------
__global__ __launch_bounds__(256, 2) void xproj_kernel(
    const float* __restrict__ x, const float* __restrict__ Wih,
    const float* __restrict__ bih, const float* __restrict__ bhh)
{
    __shared__ float xs[8][132];   // [k][m], pad 132 -> conflict-free transpose store
    __shared__ float wsm[8][132];  // [k][n]

    const int tid = threadIdx.x;
    const int tx = tid & 15;       // n direction
    const int ty = tid >> 4;       // m direction
    const int m0 = blockIdx.y << 7;
    const int n0 = blockIdx.x << 7;
    const int lrow = tid >> 1;         // 0..127
    const int lkq  = (tid & 1) << 2;   // 0 or 4

    const float* aptr = x   + (size_t)(m0 + lrow) * INDIM + lkq;
    const float* bptr = Wih + (size_t)(n0 + lrow) * INDIM + lkq;

    float acc[8][8];
#pragma unroll
    for (int u = 0; u < 8; u++)
#pragma unroll
        for (int v = 0; v < 8; v++) acc[u][v] = 0.f;

    float4 ra = *(const float4*)aptr;
    float4 rb = *(const float4*)bptr;

    for (int k0 = 0; k0 < INDIM; k0 += 8) {
        __syncthreads();
        xs[lkq + 0][lrow] = ra.x;  xs[lkq + 1][lrow] = ra.y;
        xs[lkq + 2][lrow] = ra.z;  xs[lkq + 3][lrow] = ra.w;
        wsm[lkq + 0][lrow] = rb.x; wsm[lkq + 1][lrow] = rb.y;
        wsm[lkq + 2][lrow] = rb.z; wsm[lkq + 3][lrow] = rb.w;
        __syncthreads();
        if (k0 + 8 < INDIM) {
            ra = *(const float4*)(aptr + k0 + 8);
            rb = *(const float4*)(bptr + k0 + 8);
        }
#pragma unroll
        for (int k = 0; k < 8; k++) {
            float a[8], b[8];
            *(float4*)&a[0] = *(const float4*)&xs[k][ty * 4];
            *(float4*)&a[4] = *(const float4*)&xs[k][64 + ty * 4];
            *(float4*)&b[0] = *(const float4*)&wsm[k][tx * 4];
            *(float4*)&b[4] = *(const float4*)&wsm[k][64 + tx * 4];
#pragma unroll
            for (int u = 0; u < 8; u++)
#pragma unroll
                for (int v = 0; v < 8; v++)
                    acc[u][v] = fmaf(a[u], b[v], acc[u][v]);
        }
    }

    // Epilogue: add bias, store transposed xprojT[t][n][b]
    const int t = m0 >> 7;
#pragma unroll
    for (int v = 0; v < 8; v++) {
        const int n = n0 + ((v < 4) ? (tx * 4 + v) : (64 + tx * 4 + (v - 4)));
        const float bias = bih[n] + bhh[n];
        float* dst = g_xprojT + ((size_t)t * GATES + n) * BATCH;
        float4 o0 = make_float4(acc[0][v] + bias, acc[1][v] + bias,
                                acc[2][v] + bias, acc[3][v] + bias);
        float4 o1 = make_float4(acc[4][v] + bias, acc[5][v] + bias,
                                acc[6][v] + bias, acc[7][v] + bias);
        *(float4*)(dst + ty * 4)      = o0;
        *(float4*)(dst + 64 + ty * 4) = o1;
    }
}

// ---------------------------------------------------------------------------
// Phase 2: persistent recurrence. 128 blocks x 128 threads.
// Block bid owns hidden columns j0..j0+3 (j0 = 4*bid) and the 16 W_hh rows
// {gt*512 + j0 + u} which stay resident in SMEM (k-major) for all 1024 steps.
// Warp gq (= gate type) computes z for its gate across all 128 batches.
// h double-buffered in global as hT[k][b]; one grid barrier per step.
// ---------------------------------------------------------------------------
__global__ __launch_bounds__(128) void rec_kernel(
    const float* __restrict__ Whh, float* __restrict__ out)
{
    extern __shared__ float smem[];
    float* wsl = smem;               // [512][16]  W slice, k-major
    float* hs  = smem + 512 * 16;    // [128][128] h chunk, k-major
    float* zs  = hs + 128 * 128;     // [16][132]  z exchange (pad for banks)

    const int tid  = threadIdx.x;
    const int bid  = blockIdx.x;
    const int gq   = tid >> 5;    // warp id = gate type (i,f,o,g)
    const int lane = tid & 31;
    const int j0   = bid << 2;

    // One-time: load W_hh slice into SMEM, k-major: wsl[k*16 + gt*4+u]
    {
        const int r   = tid >> 3;   // 0..15 slice row
        const int seg = tid & 7;
        const int gt  = r >> 2;
        const int u   = r & 3;
        const float* wr = Whh + (size_t)(gt * HID + j0 + u) * HID + seg * 64;
        for (int k = 0; k < 64; k++)
            wsl[(seg * 64 + k) * 16 + r] = wr[k];
    }

    // Zero initial h buffer (cooperative across grid)
    for (int i = bid * 128 + tid; i < HID * BATCH; i += 128 * 128)
        g_hT[0][i] = 0.f;
    __threadfence();
    grid_barrier(128);

    float creg[4] = {0.f, 0.f, 0.f, 0.f};
    float hreg[4] = {0.f, 0.f, 0.f, 0.f};

    for (int t = 0; t < TSTEPS; t++) {
        const float* hread  = g_hT[t & 1];
        float*       hwrite = g_hT[(t + 1) & 1];

        // init accumulators with xproj (+biases already folded in)
        float acc[4][4];
#pragma unroll
        for (int u = 0; u < 4; u++) {
            const float4 xv = *(const float4*)(g_xprojT +
                ((size_t)t * GATES + gq * HID + j0 + u) * BATCH + lane * 4);
            acc[u][0] = xv.x; acc[u][1] = xv.y; acc[u][2] = xv.z; acc[u][3] = xv.w;
        }

        // z += W_slice @ h   (K in 4 chunks of 128, staged through SMEM)
        for (int kc = 0; kc < HID; kc += 128) {
            __syncthreads();
            const float* src = hread + kc * BATCH;   // contiguous copy
#pragma unroll
            for (int i = 0; i < 32; i++) {
                const int idx = (i * 128 + tid) * 4;
                *(float4*)(hs + idx) = *(const float4*)(src + idx);
            }
            __syncthreads();
#pragma unroll 8
            for (int k = 0; k < 128; k++) {
                const float4 wv = *(const float4*)(wsl + (kc + k) * 16 + gq * 4); // broadcast
                const float4 hv = *(const float4*)(hs + k * 128 + lane * 4);
                acc[0][0] = fmaf(wv.x, hv.x, acc[0][0]);
                acc[0][1] = fmaf(wv.x, hv.y, acc[0][1]);
                acc[0][2] = fmaf(wv.x, hv.z, acc[0][2]);
                acc[0][3] = fmaf(wv.x, hv.w, acc[0][3]);
                acc[1][0] = fmaf(wv.y, hv.x, acc[1][0]);
                acc[1][1] = fmaf(wv.y, hv.y, acc[1][1]);
                acc[1][2] = fmaf(wv.y, hv.z, acc[1][2]);
                acc[1][3] = fmaf(wv.y, hv.w, acc[1][3]);
                acc[2][0] = fmaf(wv.z, hv.x, acc[2][0]);
                acc[2][1] = fmaf(wv.z, hv.y, acc[2][1]);
                acc[2][2] = fmaf(wv.z, hv.z, acc[2][2]);
                acc[2][3] = fmaf(wv.z, hv.w, acc[2][3]);
                acc[3][0] = fmaf(wv.w, hv.x, acc[3][0]);
                acc[3][1] = fmaf(wv.w, hv.y, acc[3][1]);
                acc[3][2] = fmaf(wv.w, hv.z, acc[3][2]);
                acc[3][3] = fmaf(wv.w, hv.w, acc[3][3]);
            }
        }

        // exchange z through SMEM so thread b owns all 4 gates of its columns
#pragma unroll
        for (int u = 0; u < 4; u++) {
            *(float4*)(zs + (gq * 4 + u) * 132 + lane * 4) =
                make_float4(acc[u][0], acc[u][1], acc[u][2], acc[u][3]);
        }
        __syncthreads();

        // gate nonlinearities + state update: thread == batch element
        {
            const int b = tid;
#pragma unroll
            for (int j = 0; j < 4; j++) {
                const float zi = zs[( 0 + j) * 132 + b];
                const float zf = zs[( 4 + j) * 132 + b];
                const float zo = zs[( 8 + j) * 132 + b];
                const float zg = zs[(12 + j) * 132 + b];
                const float ig = 1.f / (1.f + expf(-zi));
                const float fg = 1.f / (1.f + expf(-zf));
                const float og = 1.f / (1.f + expf(-zo));
                const float gg = tanhf(zg);
                const float c  = fg * creg[j] + ig * gg;
                creg[j] = c;
                const float h = og * tanhf(c);
                hreg[j] = h;
                hwrite[(j0 + j) * BATCH + b] = h;                       // hT for next step
                out[((size_t)t * BATCH + b) * HID + j0 + j] = h;        // output[t][b][j]
            }
        }
        __threadfence();
        grid_barrier(128);
    }

    // Final (h, c) appended after output: [T*B*H] | h[B*H] | c[B*H]
    {
        const int b = tid;
        const size_t oh = (size_t)TSTEPS * BATCH * HID;
#pragma unroll
        for (int j = 0; j < 4; j++) {
            out[oh + (size_t)b * HID + j0 + j]                         = hreg[j];
            out[oh + (size_t)BATCH * HID + (size_t)b * HID + j0 + j]   = creg[j];
        }
    }
}

// ---------------------------------------------------------------------------
extern "C" void kernel_launch(void* const* d_in, const int* in_sizes, int n_in,
                              void* d_out, int out_size) {
    const float* x    = (const float*)d_in[0];
    const float* Wih  = (const float*)d_in[1];
    const float* bih  = (const float*)d_in[2];
    const float* Whh  = (const float*)d_in[3];
    const float* bhh  = (const float*)d_in[4];
    float* out = (float*)d_out;
    (void)in_sizes; (void)n_in; (void)out_size;

    // Phase 1: xproj GEMM (parallel over all timesteps)
    dim3 g1(GATES / 128, (TSTEPS * BATCH) / 128);
    xproj_kernel<<<g1, 256>>>(x, Wih, bih, bhh);

    // Phase 2: persistent recurrence
    const int smemBytes = (512 * 16 + 128 * 128 + 16 * 132) * (int)sizeof(float);
    cudaFuncSetAttribute(rec_kernel,
                         cudaFuncAttributeMaxDynamicSharedMemorySize, smemBytes);
    rec_kernel<<<128, 128, smemBytes>>>(Whh, out);
}

// round 2
// speedup vs baseline: 1.0008x; 1.0008x over previous
#include <cuda_runtime.h>
#include <math.h>
#include <stdint.h>
#include <stddef.h>

// Problem constants
#define TSTEPS 1024
#define BATCH  128
#define INDIM  512
#define HID    512
#define GATES  2048   // 4*HID, gate order: i, f, o, g

// ---------------------------------------------------------------------------
// Device-global scratch (allocation-free kernel_launch requirement)
// ---------------------------------------------------------------------------
// xproj stored TRANSPOSED per timestep: g_xprojT[t][gate][batch]
__device__ float g_xprojT[(size_t)TSTEPS * GATES * BATCH];   // 1 GiB
// hidden state double buffer, stored transposed: [k][b]
__device__ float g_hT[2][HID * BATCH];
// grid barrier state (self-resetting: deterministic across graph replays)
__device__ unsigned g_count;
__device__ unsigned g_gen;

__device__ __forceinline__ void grid_barrier(unsigned nb) {
    __syncthreads();
    if (threadIdx.x == 0) {
        unsigned my = *(volatile unsigned*)&g_gen;
        __threadfence();
        unsigned old = atomicAdd(&g_count, 1u);
        if (old == nb - 1u) {
            atomicExch(&g_count, 0u);
            __threadfence();
            atomicAdd(&g_gen, 1u);
        } else {
            while (*(volatile unsigned*)&g_gen == my) { }
        }
        __threadfence();
    }
    __syncthreads();
}

// ---------------------------------------------------------------------------
// Phase 1: xproj[t][g][b] = sum_k x[t][b][k] * W_ih[g][k] + b_ih[g] + b_hh[g]
// Classic 128x128x8 SGEMM tile, 256 threads, 8x8 per thread (split 4+4),
// register-prefetched global loads. Both operands are K-contiguous (NT GEMM).
// BM=128 == BATCH, so each m-tile is exactly one timestep -> transposed store
// xprojT[t][n][b] is coalesced along b.
// ---------------------------------------------------------------------------
__global__ __launch_bounds__(256, 2) void xproj_kernel(
    const float* __restrict__ x, const float* __restrict__ Wih,
    const float* __restrict__ bih, const float* __restrict__ bhh)
{
    __shared__ float xs[8][132];   // [k][m], pad 132 -> conflict-free transpose store
    __shared__ float wsm[8][132];  // [k][n]

    const int tid = threadIdx.x;
    const int tx = tid & 15;       // n direction
    const int ty = tid >> 4;       // m direction
    const int m0 = blockIdx.y << 7;
    const int n0 = blockIdx.x << 7;
    const int lrow = tid >> 1;         // 0..127
    const int lkq  = (tid & 1) << 2;   // 0 or 4

    const float* aptr = x   + (size_t)(m0 + lrow) * INDIM + lkq;
    const float* bptr = Wih + (size_t)(n0 + lrow) * INDIM + lkq;

    float acc[8][8];
#pragma unroll
    for (int u = 0; u < 8; u++)
#pragma unroll
        for (int v = 0; v < 8; v++) acc[u][v] = 0.f;

    float4 ra = *(const float4*)aptr;
    float4 rb = *(const float4*)bptr;

    for (int k0 = 0; k0 < INDIM; k0 += 8) {
        __syncthreads();
        xs[lkq + 0][lrow] = ra.x;  xs[lkq + 1][lrow] = ra.y;
        xs[lkq + 2][lrow] = ra.z;  xs[lkq + 3][lrow] = ra.w;
        wsm[lkq + 0][lrow] = rb.x; wsm[lkq + 1][lrow] = rb.y;
        wsm[lkq + 2][lrow] = rb.z; wsm[lkq + 3][lrow] = rb.w;
        __syncthreads();
        if (k0 + 8 < INDIM) {
            ra = *(const float4*)(aptr + k0 + 8);
            rb = *(const float4*)(bptr + k0 + 8);
        }
#pragma unroll
        for (int k = 0; k < 8; k++) {
            float a[8], b[8];
            *(float4*)&a[0] = *(const float4*)&xs[k][ty * 4];
            *(float4*)&a[4] = *(const float4*)&xs[k][64 + ty * 4];
            *(float4*)&b[0] = *(const float4*)&wsm[k][tx * 4];
            *(float4*)&b[4] = *(const float4*)&wsm[k][64 + tx * 4];
#pragma unroll
            for (int u = 0; u < 8; u++)
#pragma unroll
                for (int v = 0; v < 8; v++)
                    acc[u][v] = fmaf(a[u], b[v], acc[u][v]);
        }
    }

    // Epilogue: add bias, store transposed xprojT[t][n][b]
    const int t = m0 >> 7;
#pragma unroll
    for (int v = 0; v < 8; v++) {
        const int n = n0 + ((v < 4) ? (tx * 4 + v) : (64 + tx * 4 + (v - 4)));
        const float bias = bih[n] + bhh[n];
        float* dst = g_xprojT + ((size_t)t * GATES + n) * BATCH;
        float4 o0 = make_float4(acc[0][v] + bias, acc[1][v] + bias,
                                acc[2][v] + bias, acc[3][v] + bias);
        float4 o1 = make_float4(acc[4][v] + bias, acc[5][v] + bias,
                                acc[6][v] + bias, acc[7][v] + bias);
        *(float4*)(dst + ty * 4)      = o0;
        *(float4*)(dst + 64 + ty * 4) = o1;
    }
}

// ---------------------------------------------------------------------------
// Phase 2: persistent recurrence. 128 blocks x 128 threads.
// Block bid owns hidden columns j0..j0+3 (j0 = 4*bid) and the 16 W_hh rows
// {gt*512 + j0 + u} which stay resident in SMEM (k-major) for all 1024 steps.
// Warp gq (= gate type) computes z for its gate across all 128 batches.
// h double-buffered in global as hT[k][b]; one grid barrier per step.
// ---------------------------------------------------------------------------
__global__ __launch_bounds__(128) void rec_kernel(
    const float* __restrict__ Whh, float* __restrict__ out)
{
    extern __shared__ float smem[];
    float* wsl = smem;               // [512][16]  W slice, k-major
    float* hs  = smem + 512 * 16;    // [128][128] h chunk, k-major
    float* zs  = hs + 128 * 128;     // [16][132]  z exchange (pad for banks)

    const int tid  = threadIdx.x;
    const int bid  = blockIdx.x;
    const int gq   = tid >> 5;    // warp id = gate type (i,f,o,g)
    const int lane = tid & 31;
    const int j0   = bid << 2;

    // One-time: load W_hh slice into SMEM, k-major: wsl[k*16 + gt*4+u]
    {
        const int r   = tid >> 3;   // 0..15 slice row
        const int seg = tid & 7;
        const int gt  = r >> 2;
        const int u   = r & 3;
        const float* wr = Whh + (size_t)(gt * HID + j0 + u) * HID + seg * 64;
        for (int k = 0; k < 64; k++)
            wsl[(seg * 64 + k) * 16 + r] = wr[k];
    }

    // Zero initial h buffer (cooperative across grid)
    for (int i = bid * 128 + tid; i < HID * BATCH; i += 128 * 128)
        g_hT[0][i] = 0.f;
    __threadfence();
    grid_barrier(128);

    float creg[4] = {0.f, 0.f, 0.f, 0.f};
    float hreg[4] = {0.f, 0.f, 0.f, 0.f};

    for (int t = 0; t < TSTEPS; t++) {
        const float* hread  = g_hT[t & 1];
        float*       hwrite = g_hT[(t + 1) & 1];

        // init accumulators with xproj (+biases already folded in)
        float acc[4][4];
#pragma unroll
        for (int u = 0; u < 4; u++) {
            const float4 xv = *(const float4*)(g_xprojT +
                ((size_t)t * GATES + gq * HID + j0 + u) * BATCH + lane * 4);
            acc[u][0] = xv.x; acc[u][1] = xv.y; acc[u][2] = xv.z; acc[u][3] = xv.w;
        }

        // z += W_slice @ h   (K in 4 chunks of 128, staged through SMEM)
        for (int kc = 0; kc < HID; kc += 128) {
            __syncthreads();
            const float* src = hread + kc * BATCH;   // contiguous copy
#pragma unroll
            for (int i = 0; i < 32; i++) {
                const int idx = (i * 128 + tid) * 4;
                *(float4*)(hs + idx) = *(const float4*)(src + idx);
            }
            __syncthreads();
#pragma unroll 8
            for (int k = 0; k < 128; k++) {
                const float4 wv = *(const float4*)(wsl + (kc + k) * 16 + gq * 4); // broadcast
                const float4 hv = *(const float4*)(hs + k * 128 + lane * 4);
                acc[0][0] = fmaf(wv.x, hv.x, acc[0][0]);
                acc[0][1] = fmaf(wv.x, hv.y, acc[0][1]);
                acc[0][2] = fmaf(wv.x, hv.z, acc[0][2]);
                acc[0][3] = fmaf(wv.x, hv.w, acc[0][3]);
                acc[1][0] = fmaf(wv.y, hv.x, acc[1][0]);
                acc[1][1] = fmaf(wv.y, hv.y, acc[1][1]);
                acc[1][2] = fmaf(wv.y, hv.z, acc[1][2]);
                acc[1][3] = fmaf(wv.y, hv.w, acc[1][3]);
                acc[2][0] = fmaf(wv.z, hv.x, acc[2][0]);
                acc[2][1] = fmaf(wv.z, hv.y, acc[2][1]);
                acc[2][2] = fmaf(wv.z, hv.z, acc[2][2]);
                acc[2][3] = fmaf(wv.z, hv.w, acc[2][3]);
                acc[3][0] = fmaf(wv.w, hv.x, acc[3][0]);
                acc[3][1] = fmaf(wv.w, hv.y, acc[3][1]);
                acc[3][2] = fmaf(wv.w, hv.z, acc[3][2]);
                acc[3][3] = fmaf(wv.w, hv.w, acc[3][3]);
            }
        }

        // exchange z through SMEM so thread b owns all 4 gates of its columns
#pragma unroll
        for (int u = 0; u < 4; u++) {
            *(float4*)(zs + (gq * 4 + u) * 132 + lane * 4) =
                make_float4(acc[u][0], acc[u][1], acc[u][2], acc[u][3]);
        }
        __syncthreads();

        // gate nonlinearities + state update: thread == batch element
        {
            const int b = tid;
#pragma unroll
            for (int j = 0; j < 4; j++) {
                const float zi = zs[( 0 + j) * 132 + b];
                const float zf = zs[( 4 + j) * 132 + b];
                const float zo = zs[( 8 + j) * 132 + b];
                const float zg = zs[(12 + j) * 132 + b];
                const float ig = 1.f / (1.f + expf(-zi));
                const float fg = 1.f / (1.f + expf(-zf));
                const float og = 1.f / (1.f + expf(-zo));
                const float gg = tanhf(zg);
                const float c  = fg * creg[j] + ig * gg;
                creg[j] = c;
                const float h = og * tanhf(c);
                hreg[j] = h;
                hwrite[(j0 + j) * BATCH + b] = h;                       // hT for next step
                out[((size_t)t * BATCH + b) * HID + j0 + j] = h;        // output[t][b][j]
            }
        }
        __threadfence();
        grid_barrier(128);
    }

    // Final (h, c) appended after output: [T*B*H] | h[B*H] | c[B*H]
    {
        const int b = tid;
        const size_t oh = (size_t)TSTEPS * BATCH * HID;
#pragma unroll
        for (int j = 0; j < 4; j++) {
            out[oh + (size_t)b * HID + j0 + j]                         = hreg[j];
            out[oh + (size_t)BATCH * HID + (size_t)b * HID + j0 + j]   = creg[j];
        }
    }
}

// ---------------------------------------------------------------------------
extern "C" void kernel_launch(void* const* d_in, const int* in_sizes, int n_in,
                              void* d_out, int out_size) {
    const float* x    = (const float*)d_in[0];
    const float* Wih  = (const float*)d_in[1];
    const float* bih  = (const float*)d_in[2];
    const float* Whh  = (const float*)d_in[3];
    const float* bhh  = (const float*)d_in[4];
    float* out = (float*)d_out;
    (void)in_sizes; (void)n_in; (void)out_size;

    // Phase 1: xproj GEMM (parallel over all timesteps)
    dim3 g1(GATES / 128, (TSTEPS * BATCH) / 128);
    xproj_kernel<<<g1, 256>>>(x, Wih, bih, bhh);

    // Phase 2: persistent recurrence
    const int smemBytes = (512 * 16 + 128 * 128 + 16 * 132) * (int)sizeof(float);
    cudaFuncSetAttribute(rec_kernel,
                         cudaFuncAttributeMaxDynamicSharedMemorySize, smemBytes);
    rec_kernel<<<128, 128, smemBytes>>>(Whh, out);
}

// round 4
// speedup vs baseline: 1.9165x; 1.9149x over previous
#include <cuda_runtime.h>
#include <cuda_bf16.h>
#include <math.h>
#include <stdint.h>
#include <stddef.h>

#define TSTEPS 1024
#define BATCH  128
#define INDIM  512
#define HID    512
#define GATES  2048   // gate order: i, f, o, g

// ---------------------------------------------------------------------------
// Device-global scratch
// ---------------------------------------------------------------------------
__device__ float g_xprojT[(size_t)TSTEPS * GATES * BATCH];     // [t][gate][b]
__device__ float g_hT[2][HID * BATCH];                         // [k][b]
__device__ __nv_bfloat16 g_xhi[(size_t)TSTEPS * BATCH * INDIM];
__device__ __nv_bfloat16 g_xlo[(size_t)TSTEPS * BATCH * INDIM];
__device__ __nv_bfloat16 g_whi[(size_t)GATES * INDIM];
__device__ __nv_bfloat16 g_wlo[(size_t)GATES * INDIM];
__device__ unsigned g_count;
__device__ unsigned g_gen;

__device__ __forceinline__ void grid_barrier(unsigned nb) {
    __syncthreads();
    if (threadIdx.x == 0) {
        unsigned my = *(volatile unsigned*)&g_gen;
        __threadfence();
        unsigned old = atomicAdd(&g_count, 1u);
        if (old == nb - 1u) {
            atomicExch(&g_count, 0u);
            __threadfence();
            atomicAdd(&g_gen, 1u);
        } else {
            while (*(volatile unsigned*)&g_gen == my) { }
        }
        __threadfence();
    }
    __syncthreads();
}

__device__ __forceinline__ uint32_t smem_u32(const void* p) {
    uint32_t a;
    asm("{ .reg .u64 t; cvta.to.shared.u64 t, %1; cvt.u32.u64 %0, t; }"
        : "=r"(a) : "l"(p));
    return a;
}
#define CP16(dst, src) \
    asm volatile("cp.async.cg.shared.global [%0], [%1], 16;" \
                 :: "r"(dst), "l"(src) : "memory")
#define CP_COMMIT() asm volatile("cp.async.commit_group;" ::: "memory")
#define CP_WAIT(n)  asm volatile("cp.async.wait_group %0;" :: "n"(n) : "memory")

__device__ __forceinline__ void ldm4(uint32_t* r, uint32_t addr) {
    asm volatile("ldmatrix.sync.aligned.m8n8.x4.shared.b16 {%0,%1,%2,%3}, [%4];"
        : "=r"(r[0]), "=r"(r[1]), "=r"(r[2]), "=r"(r[3]) : "r"(addr));
}
__device__ __forceinline__ void mma_bf16(float* c, const uint32_t* a, const uint32_t* b) {
    asm volatile("mma.sync.aligned.m16n8k16.row.col.f32.bf16.bf16.f32 "
        "{%0,%1,%2,%3}, {%4,%5,%6,%7}, {%8,%9}, {%0,%1,%2,%3};"
        : "+f"(c[0]), "+f"(c[1]), "+f"(c[2]), "+f"(c[3])
        : "r"(a[0]), "r"(a[1]), "r"(a[2]), "r"(a[3]), "r"(b[0]), "r"(b[1]));
}

// ---------------------------------------------------------------------------
// Phase 0: split fp32 -> bf16 (hi, lo)
// ---------------------------------------------------------------------------
__global__ void split_x_kernel(const float* __restrict__ src) {
    const int n4 = (TSTEPS * BATCH * INDIM) / 4;
    for (int i = blockIdx.x * blockDim.x + threadIdx.x; i < n4;
         i += gridDim.x * blockDim.x) {
        float4 v = ((const float4*)src)[i];
        __nv_bfloat16 hx = __float2bfloat16(v.x), hy = __float2bfloat16(v.y);
        __nv_bfloat16 hz = __float2bfloat16(v.z), hw = __float2bfloat16(v.w);
        __nv_bfloat162* H = (__nv_bfloat162*)(g_xhi + (size_t)i * 4);
        H[0] = __nv_bfloat162(hx, hy); H[1] = __nv_bfloat162(hz, hw);
        __nv_bfloat162* L = (__nv_bfloat162*)(g_xlo + (size_t)i * 4);
        L[0] = __nv_bfloat162(__float2bfloat16(v.x - __bfloat162float(hx)),
                              __float2bfloat16(v.y - __bfloat162float(hy)));
        L[1] = __nv_bfloat162(__float2bfloat16(v.z - __bfloat162float(hz)),
                              __float2bfloat16(v.w - __bfloat162float(hw)));
    }
}
__global__ void split_w_kernel(const float* __restrict__ src) {
    const int n4 = (GATES * INDIM) / 4;
    for (int i = blockIdx.x * blockDim.x + threadIdx.x; i < n4;
         i += gridDim.x * blockDim.x) {
        float4 v = ((const float4*)src)[i];
        __nv_bfloat16 hx = __float2bfloat16(v.x), hy = __float2bfloat16(v.y);
        __nv_bfloat16 hz = __float2bfloat16(v.z), hw = __float2bfloat16(v.w);
        __nv_bfloat162* H = (__nv_bfloat162*)(g_whi + (size_t)i * 4);
        H[0] = __nv_bfloat162(hx, hy); H[1] = __nv_bfloat162(hz, hw);
        __nv_bfloat162* L = (__nv_bfloat162*)(g_wlo + (size_t)i * 4);
        L[0] = __nv_bfloat162(__float2bfloat16(v.x - __bfloat162float(hx)),
                              __float2bfloat16(v.y - __bfloat162float(hy)));
        L[1] = __nv_bfloat162(__float2bfloat16(v.z - __bfloat162float(hz)),
                              __float2bfloat16(v.w - __bfloat162float(hw)));
    }
}

// ---------------------------------------------------------------------------
// Phase 1: xproj GEMM via mma.sync bf16 3-split. CTA tile 128(M=batch of one
// timestep) x 128(N=gates), K chunks of 32. 8 warps = 2(M) x 4(N), warp tile
// 64x32. SMEM rows stride 80B (conflict-free ldmatrix: 80r mod 128 is a
// permutation of 16B slots). cp.async double-buffer. Epilogue staged in SMEM
// for coalesced transposed store xprojT[t][n][b].
// ---------------------------------------------------------------------------
#define XB_BUF    1024
#define XB_STAGE  40960             // 4 tiles x 128 rows x 80B
#define XB_AH     0
#define XB_AL     10240
#define XB_BH     20480
#define XB_BL     30720
#define SMEM_XP   (XB_BUF + 2 * XB_STAGE)   // 82944 B (epilogue reuses buffers)

__global__ __launch_bounds__(256) void xproj_mma_kernel(
    const float* __restrict__ bih, const float* __restrict__ bhh)
{
    extern __shared__ char sm[];
    const uint32_t smb = smem_u32(sm);
    float* bias = (float*)sm;
    const int tid = threadIdx.x, wid = tid >> 5, lane = tid & 31;
    const int mw = wid & 1, nw = wid >> 1;
    const int t = blockIdx.y;
    const int n0 = blockIdx.x * 128;

    if (tid < 128) bias[tid] = bih[n0 + tid] + bhh[n0 + tid];

    float acc[4][4][4];
#pragma unroll
    for (int a = 0; a < 4; a++)
#pragma unroll
        for (int b = 0; b < 4; b++)
#pragma unroll
            for (int q = 0; q < 4; q++) acc[a][b][q] = 0.f;

    // ldmatrix lane addressing
    const int arow = ((lane >> 3) & 1) * 8 + (lane & 7);
    const int ach  = lane >> 4;
    const int brow = ((lane >> 4) & 1) * 8 + (lane & 7);
    const int bch  = (lane >> 3) & 1;

#define XP_ISSUE(s_, c_) do {                                                  \
    _Pragma("unroll")                                                          \
    for (int j_ = 0; j_ < 2; j_++) {                                           \
        const int u_ = j_ * 256 + tid;                                         \
        const int r_ = u_ >> 2, cc_ = u_ & 3;                                  \
        const size_t gx_ = ((size_t)t * 128 + r_) * INDIM + (c_) * 32 + cc_ * 8; \
        const size_t gw_ = (size_t)(n0 + r_) * INDIM + (c_) * 32 + cc_ * 8;    \
        const uint32_t db_ = smb + XB_BUF + (s_) * XB_STAGE + r_ * 80 + cc_ * 16; \
        CP16(db_ + XB_AH, g_xhi + gx_);                                        \
        CP16(db_ + XB_AL, g_xlo + gx_);                                        \
        CP16(db_ + XB_BH, g_whi + gw_);                                        \
        CP16(db_ + XB_BL, g_wlo + gw_);                                        \
    }                                                                          \
    CP_COMMIT();                                                               \
} while (0)

    XP_ISSUE(0, 0);
#pragma unroll 1
    for (int c = 0; c < 16; c++) {
        if (c < 15) { XP_ISSUE((c + 1) & 1, c + 1); CP_WAIT(1); }
        else        { CP_WAIT(0); }
        __syncthreads();
        const uint32_t base = smb + XB_BUF + (c & 1) * XB_STAGE;
#pragma unroll
        for (int h = 0; h < 2; h++) {
            uint32_t ah[4][4], al[4][4], bhf[2][4], blf[2][4];
#pragma unroll
            for (int mt = 0; mt < 4; mt++) {
                const uint32_t aA = base + XB_AH +
                    (uint32_t)(mw * 64 + mt * 16 + arow) * 80 + (h * 2 + ach) * 16;
                ldm4(ah[mt], aA);
                ldm4(al[mt], aA + (XB_AL - XB_AH));
            }
#pragma unroll
            for (int bt = 0; bt < 2; bt++) {
                const uint32_t aB = base + XB_BH +
                    (uint32_t)(nw * 32 + bt * 16 + brow) * 80 + (h * 2 + bch) * 16;
                ldm4(bhf[bt], aB);
                ldm4(blf[bt], aB + (XB_BL - XB_BH));
            }
#pragma unroll
            for (int mt = 0; mt < 4; mt++)
#pragma unroll
                for (int bt = 0; bt < 2; bt++) {
                    mma_bf16(acc[mt][bt * 2 + 0], ah[mt], bhf[bt] + 0);
                    mma_bf16(acc[mt][bt * 2 + 1], ah[mt], bhf[bt] + 2);
                    mma_bf16(acc[mt][bt * 2 + 0], ah[mt], blf[bt] + 0);
                    mma_bf16(acc[mt][bt * 2 + 1], ah[mt], blf[bt] + 2);
                    mma_bf16(acc[mt][bt * 2 + 0], al[mt], bhf[bt] + 0);
                    mma_bf16(acc[mt][bt * 2 + 1], al[mt], bhf[bt] + 2);
                }
        }
        __syncthreads();
    }

    // Epilogue: fragments -> SMEM [n][b] (pad 132), + bias, then coalesced store
    float* ep = (float*)(sm + XB_BUF);
    const int g = lane >> 2, tg2 = (lane & 3) * 2;
#pragma unroll
    for (int mt = 0; mt < 4; mt++)
#pragma unroll
        for (int nt = 0; nt < 4; nt++) {
            const int bb = mw * 64 + mt * 16 + g;
            const int nn = nw * 32 + nt * 8 + tg2;
            ep[(nn)     * 132 + bb]     = acc[mt][nt][0] + bias[nn];
            ep[(nn + 1) * 132 + bb]     = acc[mt][nt][1] + bias[nn + 1];
            ep[(nn)     * 132 + bb + 8] = acc[mt][nt][2] + bias[nn];
            ep[(nn + 1) * 132 + bb + 8] = acc[mt][nt][3] + bias[nn + 1];
        }
    __syncthreads();
#pragma unroll
    for (int j = 0; j < 16; j++) {
        const int idx = j * 256 + tid;
        const int n = idx >> 5, q = idx & 31;
        const float4 v = *(const float4*)(ep + n * 132 + q * 4);
        *(float4*)(g_xprojT + ((size_t)t * GATES + n0 + n) * BATCH + q * 4) = v;
    }
}

// ---------------------------------------------------------------------------
// Phase 2: persistent recurrence, fp32. 128 blocks x 256 threads (8 warps).
// Warp (gq = wid&3, kh = wid>>2): gate gq, K half kh. W slice resident in
// SMEM; h staged via cp.async.cg (L2-coherent) in a 2-stage pipeline.
// ---------------------------------------------------------------------------
#define R_WSL 0
#define R_HS  8192
#define R_ZS  (8192 + 32768)
#define SMEM_REC ((8192 + 32768 + 2 * 16 * 132) * 4)

__global__ __launch_bounds__(256) void rec2_kernel(
    const float* __restrict__ Whh, float* __restrict__ out)
{
    extern __shared__ float smem[];
    float* wsl = smem + R_WSL;
    float* hs  = smem + R_HS;
    float* zs  = smem + R_ZS;
    const uint32_t hs_u32 = smem_u32(hs);

    const int tid = threadIdx.x, bid = blockIdx.x;
    const int wid = tid >> 5, lane = tid & 31;
    const int gq = wid & 3, kh = wid >> 2;
    const int j0 = bid << 2;

    {
        const int r = tid >> 4, seg = tid & 15;
        const int gt = r >> 2, u = r & 3;
        const float* wr = Whh + (size_t)(gt * HID + j0 + u) * HID + seg * 32;
#pragma unroll
        for (int k = 0; k < 32; k++) wsl[(seg * 32 + k) * 16 + r] = wr[k];
    }
    for (int i = bid * 256 + tid; i < HID * BATCH; i += 128 * 256) g_hT[0][i] = 0.f;
    __threadfence();
    grid_barrier(128);

    float creg[4] = {0, 0, 0, 0}, hreg[4] = {0, 0, 0, 0};

#define ISSUE_COPY(i_, b_) do {                                                 \
    _Pragma("unroll")                                                           \
    for (int s_ = 0; s_ < 2; s_++) {                                            \
        const float* src_ = hread + (s_ * 256 + (i_) * 64) * 128;               \
        const uint32_t dst_ = hs_u32 + (uint32_t)(((b_) * 2 + s_) * 64 * 128) * 4u; \
        _Pragma("unroll")                                                       \
        for (int j_ = 0; j_ < 8; j_++) {                                        \
            const int u_ = j_ * 256 + tid;                                      \
            CP16(dst_ + u_ * 16, src_ + u_ * 4);                                \
        }                                                                       \
    }                                                                           \
    CP_COMMIT();                                                                \
} while (0)

    for (int t = 0; t < TSTEPS; t++) {
        const float* hread  = g_hT[t & 1];
        float*       hwrite = g_hT[(t + 1) & 1];

        float acc[4][4];
        if (kh == 0) {
#pragma unroll
            for (int u = 0; u < 4; u++) {
                const float4 xv = *(const float4*)(g_xprojT +
                    ((size_t)t * GATES + gq * HID + j0 + u) * BATCH + lane * 4);
                acc[u][0] = xv.x; acc[u][1] = xv.y; acc[u][2] = xv.z; acc[u][3] = xv.w;
            }
        } else {
#pragma unroll
            for (int u = 0; u < 4; u++)
#pragma unroll
                for (int v = 0; v < 4; v++) acc[u][v] = 0.f;
        }

        ISSUE_COPY(0, 0);
#pragma unroll 1
        for (int i = 0; i < 4; i++) {
            const int b = i & 1;
            __syncthreads();                    // buffer-reuse guard
            if (i < 3) {
                ISSUE_COPY(i + 1, (i + 1) & 1);
                CP_WAIT(1);
            } else {
                CP_WAIT(0);
            }
            __syncthreads();
            const float* hp = hs + (b * 2 + kh) * 64 * 128;
            const int kb = kh * 256 + i * 64;
#pragma unroll 8
            for (int k = 0; k < 64; k++) {
                const float4 wv = *(const float4*)(wsl + (kb + k) * 16 + gq * 4);
                const float4 hv = *(const float4*)(hp + k * 128 + lane * 4);
                acc[0][0] = fmaf(wv.x, hv.x, acc[0][0]);
                acc[0][1] = fmaf(wv.x, hv.y, acc[0][1]);
                acc[0][2] = fmaf(wv.x, hv.z, acc[0][2]);
                acc[0][3] = fmaf(wv.x, hv.w, acc[0][3]);
                acc[1][0] = fmaf(wv.y, hv.x, acc[1][0]);
                acc[1][1] = fmaf(wv.y, hv.y, acc[1][1]);
                acc[1][2] = fmaf(wv.y, hv.z, acc[1][2]);
                acc[1][3] = fmaf(wv.y, hv.w, acc[1][3]);
                acc[2][0] = fmaf(wv.z, hv.x, acc[2][0]);
                acc[2][1] = fmaf(wv.z, hv.y, acc[2][1]);
                acc[2][2] = fmaf(wv.z, hv.z, acc[2][2]);
                acc[2][3] = fmaf(wv.z, hv.w, acc[2][3]);
                acc[3][0] = fmaf(wv.w, hv.x, acc[3][0]);
                acc[3][1] = fmaf(wv.w, hv.y, acc[3][1]);
                acc[3][2] = fmaf(wv.w, hv.z, acc[3][2]);
                acc[3][3] = fmaf(wv.w, hv.w, acc[3][3]);
            }
        }

#pragma unroll
        for (int u = 0; u < 4; u++)
            *(float4*)(zs + (kh * 16 + gq * 4 + u) * 132 + lane * 4) =
                make_float4(acc[u][0], acc[u][1], acc[u][2], acc[u][3]);
        __syncthreads();

        if (tid < 128) {
            const int b = tid;
#pragma unroll
            for (int j = 0; j < 4; j++) {
                const float zi = zs[( 0 + j) * 132 + b] + zs[(16 +  0 + j) * 132 + b];
                const float zf = zs[( 4 + j) * 132 + b] + zs[(16 +  4 + j) * 132 + b];
                const float zo = zs[( 8 + j) * 132 + b] + zs[(16 +  8 + j) * 132 + b];
                const float zg = zs[(12 + j) * 132 + b] + zs[(16 + 12 + j) * 132 + b];
                const float ig = 1.f / (1.f + expf(-zi));
                const float fg = 1.f / (1.f + expf(-zf));
                const float og = 1.f / (1.f + expf(-zo));
                const float gg = tanhf(zg);
                const float c  = fg * creg[j] + ig * gg;
                creg[j] = c;
                const float h = og * tanhf(c);
                hreg[j] = h;
                hwrite[(j0 + j) * BATCH + b] = h;
            }
            *(float4*)(out + ((size_t)t * BATCH + b) * HID + j0) =
                make_float4(hreg[0], hreg[1], hreg[2], hreg[3]);
            __threadfence();
        }
        grid_barrier(128);
    }

    if (tid < 128) {
        const int b = tid;
        const size_t oh = (size_t)TSTEPS * BATCH * HID;
        *(float4*)(out + oh + (size_t)b * HID + j0) =
            make_float4(hreg[0], hreg[1], hreg[2], hreg[3]);
        *(float4*)(out + oh + (size_t)BATCH * HID + (size_t)b * HID + j0) =
            make_float4(creg[0], creg[1], creg[2], creg[3]);
    }
}

// ---------------------------------------------------------------------------
extern "C" void kernel_launch(void* const* d_in, const int* in_sizes, int n_in,
                              void* d_out, int out_size) {
    const float* x   = (const float*)d_in[0];
    const float* Wih = (const float*)d_in[1];
    const float* bih = (const float*)d_in[2];
    const float* Whh = (const float*)d_in[3];
    const float* bhh = (const float*)d_in[4];
    float* out = (float*)d_out;
    (void)in_sizes; (void)n_in; (void)out_size;

    split_x_kernel<<<4096, 256>>>(x);
    split_w_kernel<<<512, 256>>>(Wih);

    cudaFuncSetAttribute(xproj_mma_kernel,
                         cudaFuncAttributeMaxDynamicSharedMemorySize, SMEM_XP);
    dim3 g1(GATES / 128, TSTEPS);
    xproj_mma_kernel<<<g1, 256, SMEM_XP>>>(bih, bhh);

    cudaFuncSetAttribute(rec2_kernel,
                         cudaFuncAttributeMaxDynamicSharedMemorySize, SMEM_REC);
    rec2_kernel<<<128, 256, SMEM_REC>>>(Whh, out);
}

// round 5
// speedup vs baseline: 2.1968x; 1.1463x over previous
#include <cuda_runtime.h>
#include <cuda_bf16.h>
#include <math.h>
#include <stdint.h>
#include <stddef.h>

#define TSTEPS 1024
#define BATCH  128
#define INDIM  512
#define HID    512
#define GATES  2048   // gate order: i, f, o, g

// ---------------------------------------------------------------------------
// Device-global scratch
// ---------------------------------------------------------------------------
__device__ float g_xprojT[(size_t)TSTEPS * GATES * BATCH];     // [t][gate][b]
__device__ __nv_bfloat16 g_hhi[HID * BATCH];                   // h split, [k][b]
__device__ __nv_bfloat16 g_hlo[HID * BATCH];
__device__ __nv_bfloat16 g_xhi[(size_t)TSTEPS * BATCH * INDIM];
__device__ __nv_bfloat16 g_xlo[(size_t)TSTEPS * BATCH * INDIM];
__device__ __nv_bfloat16 g_whi[(size_t)GATES * INDIM];
__device__ __nv_bfloat16 g_wlo[(size_t)GATES * INDIM];
__device__ unsigned g_count;
__device__ unsigned g_gen;

__device__ __forceinline__ void grid_barrier(unsigned nb) {
    __syncthreads();
    if (threadIdx.x == 0) {
        unsigned my = *(volatile unsigned*)&g_gen;
        __threadfence();
        unsigned old = atomicAdd(&g_count, 1u);
        if (old == nb - 1u) {
            atomicExch(&g_count, 0u);
            __threadfence();
            atomicAdd(&g_gen, 1u);
        } else {
            while (*(volatile unsigned*)&g_gen == my) { }
        }
        __threadfence();
    }
    __syncthreads();
}

__device__ __forceinline__ uint32_t smem_u32(const void* p) {
    uint32_t a;
    asm("{ .reg .u64 t; cvta.to.shared.u64 t, %1; cvt.u32.u64 %0, t; }"
        : "=r"(a) : "l"(p));
    return a;
}
#define CP16(dst, src) \
    asm volatile("cp.async.cg.shared.global [%0], [%1], 16;" \
                 :: "r"(dst), "l"(src) : "memory")
#define CP_COMMIT() asm volatile("cp.async.commit_group;" ::: "memory")
#define CP_WAIT(n)  asm volatile("cp.async.wait_group %0;" :: "n"(n) : "memory")

__device__ __forceinline__ void ldm4(uint32_t* r, uint32_t addr) {
    asm volatile("ldmatrix.sync.aligned.m8n8.x4.shared.b16 {%0,%1,%2,%3}, [%4];"
        : "=r"(r[0]), "=r"(r[1]), "=r"(r[2]), "=r"(r[3]) : "r"(addr));
}
__device__ __forceinline__ void ldm4t(uint32_t* r, uint32_t addr) {
    asm volatile("ldmatrix.sync.aligned.m8n8.x4.trans.shared.b16 {%0,%1,%2,%3}, [%4];"
        : "=r"(r[0]), "=r"(r[1]), "=r"(r[2]), "=r"(r[3]) : "r"(addr));
}
__device__ __forceinline__ void mma_bf16(float* c, const uint32_t* a, const uint32_t* b) {
    asm volatile("mma.sync.aligned.m16n8k16.row.col.f32.bf16.bf16.f32 "
        "{%0,%1,%2,%3}, {%4,%5,%6,%7}, {%8,%9}, {%0,%1,%2,%3};"
        : "+f"(c[0]), "+f"(c[1]), "+f"(c[2]), "+f"(c[3])
        : "r"(a[0]), "r"(a[1]), "r"(a[2]), "r"(a[3]), "r"(b[0]), "r"(b[1]));
}

// ---------------------------------------------------------------------------
// Phase 0: split fp32 -> bf16 (hi, lo)
// ---------------------------------------------------------------------------
__global__ void split_x_kernel(const float* __restrict__ src) {
    const int n4 = (TSTEPS * BATCH * INDIM) / 4;
    for (int i = blockIdx.x * blockDim.x + threadIdx.x; i < n4;
         i += gridDim.x * blockDim.x) {
        float4 v = ((const float4*)src)[i];
        __nv_bfloat16 hx = __float2bfloat16(v.x), hy = __float2bfloat16(v.y);
        __nv_bfloat16 hz = __float2bfloat16(v.z), hw = __float2bfloat16(v.w);
        __nv_bfloat162* H = (__nv_bfloat162*)(g_xhi + (size_t)i * 4);
        H[0] = __nv_bfloat162(hx, hy); H[1] = __nv_bfloat162(hz, hw);
        __nv_bfloat162* L = (__nv_bfloat162*)(g_xlo + (size_t)i * 4);
        L[0] = __nv_bfloat162(__float2bfloat16(v.x - __bfloat162float(hx)),
                              __float2bfloat16(v.y - __bfloat162float(hy)));
        L[1] = __nv_bfloat162(__float2bfloat16(v.z - __bfloat162float(hz)),
                              __float2bfloat16(v.w - __bfloat162float(hw)));
    }
}
__global__ void split_w_kernel(const float* __restrict__ src) {
    const int n4 = (GATES * INDIM) / 4;
    for (int i = blockIdx.x * blockDim.x + threadIdx.x; i < n4;
         i += gridDim.x * blockDim.x) {
        float4 v = ((const float4*)src)[i];
        __nv_bfloat16 hx = __float2bfloat16(v.x), hy = __float2bfloat16(v.y);
        __nv_bfloat16 hz = __float2bfloat16(v.z), hw = __float2bfloat16(v.w);
        __nv_bfloat162* H = (__nv_bfloat162*)(g_whi + (size_t)i * 4);
        H[0] = __nv_bfloat162(hx, hy); H[1] = __nv_bfloat162(hz, hw);
        __nv_bfloat162* L = (__nv_bfloat162*)(g_wlo + (size_t)i * 4);
        L[0] = __nv_bfloat162(__float2bfloat16(v.x - __bfloat162float(hx)),
                              __float2bfloat16(v.y - __bfloat162float(hy)));
        L[1] = __nv_bfloat162(__float2bfloat16(v.z - __bfloat162float(hz)),
                              __float2bfloat16(v.w - __bfloat162float(hw)));
    }
}

// ---------------------------------------------------------------------------
// Phase 1: xproj GEMM via mma.sync bf16 3-split (unchanged from R3: working).
// ---------------------------------------------------------------------------
#define XB_BUF    1024
#define XB_STAGE  40960
#define XB_AH     0
#define XB_AL     10240
#define XB_BH     20480
#define XB_BL     30720
#define SMEM_XP   (XB_BUF + 2 * XB_STAGE)

__global__ __launch_bounds__(256) void xproj_mma_kernel(
    const float* __restrict__ bih, const float* __restrict__ bhh)
{
    extern __shared__ char sm[];
    const uint32_t smb = smem_u32(sm);
    float* bias = (float*)sm;
    const int tid = threadIdx.x, wid = tid >> 5, lane = tid & 31;
    const int mw = wid & 1, nw = wid >> 1;
    const int t = blockIdx.y;
    const int n0 = blockIdx.x * 128;

    if (tid < 128) bias[tid] = bih[n0 + tid] + bhh[n0 + tid];

    float acc[4][4][4];
#pragma unroll
    for (int a = 0; a < 4; a++)
#pragma unroll
        for (int b = 0; b < 4; b++)
#pragma unroll
            for (int q = 0; q < 4; q++) acc[a][b][q] = 0.f;

    const int arow = ((lane >> 3) & 1) * 8 + (lane & 7);
    const int ach  = lane >> 4;
    const int brow = ((lane >> 4) & 1) * 8 + (lane & 7);
    const int bch  = (lane >> 3) & 1;

#define XP_ISSUE(s_, c_) do {                                                  \
    _Pragma("unroll")                                                          \
    for (int j_ = 0; j_ < 2; j_++) {                                           \
        const int u_ = j_ * 256 + tid;                                         \
        const int r_ = u_ >> 2, cc_ = u_ & 3;                                  \
        const size_t gx_ = ((size_t)t * 128 + r_) * INDIM + (c_) * 32 + cc_ * 8; \
        const size_t gw_ = (size_t)(n0 + r_) * INDIM + (c_) * 32 + cc_ * 8;    \
        const uint32_t db_ = smb + XB_BUF + (s_) * XB_STAGE + r_ * 80 + cc_ * 16; \
        CP16(db_ + XB_AH, g_xhi + gx_);                                        \
        CP16(db_ + XB_AL, g_xlo + gx_);                                        \
        CP16(db_ + XB_BH, g_whi + gw_);                                        \
        CP16(db_ + XB_BL, g_wlo + gw_);                                        \
    }                                                                          \
    CP_COMMIT();                                                               \
} while (0)

    XP_ISSUE(0, 0);
#pragma unroll 1
    for (int c = 0; c < 16; c++) {
        if (c < 15) { XP_ISSUE((c + 1) & 1, c + 1); CP_WAIT(1); }
        else        { CP_WAIT(0); }
        __syncthreads();
        const uint32_t base = smb + XB_BUF + (c & 1) * XB_STAGE;
#pragma unroll
        for (int h = 0; h < 2; h++) {
            uint32_t ah[4][4], al[4][4], bhf[2][4], blf[2][4];
#pragma unroll
            for (int mt = 0; mt < 4; mt++) {
                const uint32_t aA = base + XB_AH +
                    (uint32_t)(mw * 64 + mt * 16 + arow) * 80 + (h * 2 + ach) * 16;
                ldm4(ah[mt], aA);
                ldm4(al[mt], aA + (XB_AL - XB_AH));
            }
#pragma unroll
            for (int bt = 0; bt < 2; bt++) {
                const uint32_t aB = base + XB_BH +
                    (uint32_t)(nw * 32 + bt * 16 + brow) * 80 + (h * 2 + bch) * 16;
                ldm4(bhf[bt], aB);
                ldm4(blf[bt], aB + (XB_BL - XB_BH));
            }
#pragma unroll
            for (int mt = 0; mt < 4; mt++)
#pragma unroll
                for (int bt = 0; bt < 2; bt++) {
                    mma_bf16(acc[mt][bt * 2 + 0], ah[mt], bhf[bt] + 0);
                    mma_bf16(acc[mt][bt * 2 + 1], ah[mt], bhf[bt] + 2);
                    mma_bf16(acc[mt][bt * 2 + 0], ah[mt], blf[bt] + 0);
                    mma_bf16(acc[mt][bt * 2 + 1], ah[mt], blf[bt] + 2);
                    mma_bf16(acc[mt][bt * 2 + 0], al[mt], bhf[bt] + 0);
                    mma_bf16(acc[mt][bt * 2 + 1], al[mt], bhf[bt] + 2);
                }
        }
        __syncthreads();
    }

    float* ep = (float*)(sm + XB_BUF);
    const int g = lane >> 2, tg2 = (lane & 3) * 2;
#pragma unroll
    for (int mt = 0; mt < 4; mt++)
#pragma unroll
        for (int nt = 0; nt < 4; nt++) {
            const int bb = mw * 64 + mt * 16 + g;
            const int nn = nw * 32 + nt * 8 + tg2;
            ep[(nn)     * 132 + bb]     = acc[mt][nt][0] + bias[nn];
            ep[(nn + 1) * 132 + bb]     = acc[mt][nt][1] + bias[nn + 1];
            ep[(nn)     * 132 + bb + 8] = acc[mt][nt][2] + bias[nn];
            ep[(nn + 1) * 132 + bb + 8] = acc[mt][nt][3] + bias[nn + 1];
        }
    __syncthreads();
#pragma unroll
    for (int j = 0; j < 16; j++) {
        const int idx = j * 256 + tid;
        const int n = idx >> 5, q = idx & 31;
        const float4 v = *(const float4*)(ep + n * 132 + q * 4);
        *(float4*)(g_xprojT + ((size_t)t * GATES + n0 + n) * BATCH + q * 4) = v;
    }
}

// ---------------------------------------------------------------------------
// Phase 2: persistent recurrence on tensor cores (mma.sync bf16 3-split).
// 128 blocks x 256 threads. Block owns hidden j0..j0+3 -> 16 gate-rows (M=16,
// row m = gt*4+u). Warp w owns batch n0=16w (N=16). W_hh slice resident in
// SMEM as bf16 hi/lo; h published globally as bf16 hi/lo [k][b] by producers,
// consumed via cp.async.cg (L2) into double-buffered K-chunks of 128, loaded
// with ldmatrix.x4.trans (trans of h[k][b] tile == col-major B fragment).
// ---------------------------------------------------------------------------
// SMEM byte map:
#define R3_WHI   0                    // 16 rows x 520 halves (1040B stride)
#define R3_WLO   16640
#define R3_HBUF  33280                // 2 bufs x 2 comps x (128 rows x 272B)
#define R3_HB(b_, c_) (R3_HBUF + ((b_) * 2 + (c_)) * 34816)
#define R3_ZS    172544               // fp32 [16][132]
#define R3_HSTG  180992               // fp32 [4][128]
#define SMEM_REC3 183040

__global__ __launch_bounds__(256) void rec3_kernel(
    const float* __restrict__ Whh, float* __restrict__ out)
{
    extern __shared__ char sm[];
    const uint32_t smb = smem_u32(sm);
    float* zs   = (float*)(sm + R3_ZS);
    float* hstg = (float*)(sm + R3_HSTG);

    const int tid = threadIdx.x, bid = blockIdx.x;
    const int wid = tid >> 5, lane = tid & 31;
    const int j0 = bid << 2;
    const int n0 = wid << 4;             // warp's batch slice

    // W_hh slice -> SMEM bf16 hi/lo, row m = gt*4+u, stride 520 halves
    for (int i = tid; i < 16 * 512; i += 256) {
        const int m = i >> 9, k = i & 511;
        const int gr = (m >> 2) * 512 + j0 + (m & 3);
        const float w = Whh[(size_t)gr * HID + k];
        const __nv_bfloat16 wh = __float2bfloat16(w);
        ((__nv_bfloat16*)(sm + R3_WHI))[m * 520 + k] = wh;
        ((__nv_bfloat16*)(sm + R3_WLO))[m * 520 + k] =
            __float2bfloat16(w - __bfloat162float(wh));
    }
    // zero h hi/lo (one u32 per grid thread: 32768 total)
    {
        const int i = bid * 256 + tid;
        ((uint32_t*)g_hhi)[i] = 0u;
        ((uint32_t*)g_hlo)[i] = 0u;
    }
    __threadfence();
    grid_barrier(128);

    // lane addressing for ldmatrix
    const int arow = ((lane >> 3) & 1) * 8 + (lane & 7);
    const int ach  = lane >> 4;
    const uint32_t aoff = smb + R3_WHI + (uint32_t)arow * 1040 + ach * 16;
    const int krow = ((lane >> 3) & 1) * 8 + (lane & 7);
    const uint32_t bcoloff = (uint32_t)(n0 + (lane >> 4) * 8) * 2;
    // D / xproj lane addressing
    const int drow = lane >> 2, dcol = (lane & 3) * 2;

    const int b_ = tid & 127, ug = (tid >> 7) * 2;
    float creg[2] = {0.f, 0.f}, hreg[2] = {0.f, 0.f};

#define REC_ISSUE(c_, bb_) do {                                                \
    _Pragma("unroll")                                                          \
    for (int j_ = 0; j_ < 8; j_++) {                                           \
        const int u_ = j_ * 256 + tid;                                         \
        const int r_ = u_ >> 4, cc_ = u_ & 15;                                 \
        const uint32_t d_ = smb + R3_HB(bb_, 0) + r_ * 272 + cc_ * 16;         \
        const size_t s_ = ((size_t)(c_) * 128 + r_) * 128 + cc_ * 8;           \
        CP16(d_, g_hhi + s_);                                                  \
        CP16(d_ + 34816, g_hlo + s_);                                          \
    }                                                                          \
    CP_COMMIT();                                                               \
} while (0)

    for (int t = 0; t < TSTEPS; t++) {
        REC_ISSUE(0, 0);
        REC_ISSUE(1, 1);

        // acc init from xproj (z = xproj + W_hh h)
        float acc[2][4];
        {
            const float* p0 = g_xprojT +
                ((size_t)t * GATES + (drow >> 2) * 512 + j0 + (drow & 3)) * BATCH
                + n0 + dcol;
            const int r8 = drow + 8;
            const float* p8 = g_xprojT +
                ((size_t)t * GATES + (r8 >> 2) * 512 + j0 + (r8 & 3)) * BATCH
                + n0 + dcol;
            float2 v;
            v = *(const float2*)(p0);     acc[0][0] = v.x; acc[0][1] = v.y;
            v = *(const float2*)(p8);     acc[0][2] = v.x; acc[0][3] = v.y;
            v = *(const float2*)(p0 + 8); acc[1][0] = v.x; acc[1][1] = v.y;
            v = *(const float2*)(p8 + 8); acc[1][2] = v.x; acc[1][3] = v.y;
        }

#pragma unroll 1
        for (int c = 0; c < 4; c++) {
            const int bb = c & 1;
            if (c < 3) CP_WAIT(1); else CP_WAIT(0);
            __syncthreads();
#pragma unroll
            for (int kq = 0; kq < 8; kq++) {
                const int k16 = c * 8 + kq;
                uint32_t ahi[4], alo[4], bhi[4], blo[4];
                ldm4(ahi, aoff + k16 * 32);
                ldm4(alo, aoff + k16 * 32 + (R3_WLO - R3_WHI));
                const uint32_t ba = smb + R3_HB(bb, 0)
                    + (uint32_t)(kq * 16 + krow) * 272 + bcoloff;
                ldm4t(bhi, ba);
                ldm4t(blo, ba + 34816);
                mma_bf16(acc[0], ahi, bhi + 0);
                mma_bf16(acc[1], ahi, bhi + 2);
                mma_bf16(acc[0], ahi, blo + 0);
                mma_bf16(acc[1], ahi, blo + 2);
                mma_bf16(acc[0], alo, bhi + 0);
                mma_bf16(acc[1], alo, bhi + 2);
            }
            __syncthreads();               // all warps done with buffer bb
            if (c < 2) REC_ISSUE(c + 2, bb);
        }

        // dump z fragments to SMEM [m][b]
        {
            const int nc = n0 + dcol;
            *(float2*)&zs[drow * 132 + nc]           = make_float2(acc[0][0], acc[0][1]);
            *(float2*)&zs[(drow + 8) * 132 + nc]     = make_float2(acc[0][2], acc[0][3]);
            *(float2*)&zs[drow * 132 + nc + 8]       = make_float2(acc[1][0], acc[1][1]);
            *(float2*)&zs[(drow + 8) * 132 + nc + 8] = make_float2(acc[1][2], acc[1][3]);
        }
        __syncthreads();

        // gates: thread handles (u = ug+q, b = b_)
#pragma unroll
        for (int q = 0; q < 2; q++) {
            const int u = ug + q;
            const float zi = zs[( 0 + u) * 132 + b_];
            const float zf = zs[( 4 + u) * 132 + b_];
            const float zo = zs[( 8 + u) * 132 + b_];
            const float zg = zs[(12 + u) * 132 + b_];
            const float ig = 1.f / (1.f + expf(-zi));
            const float fg = 1.f / (1.f + expf(-zf));
            const float og = 1.f / (1.f + expf(-zo));
            const float gg = tanhf(zg);
            const float cc = fg * creg[q] + ig * gg;
            creg[q] = cc;
            const float h = og * tanhf(cc);
            hreg[q] = h;
            hstg[u * 128 + b_] = h;
            const __nv_bfloat16 hh = __float2bfloat16(h);
            g_hhi[(j0 + u) * BATCH + b_] = hh;
            g_hlo[(j0 + u) * BATCH + b_] =
                __float2bfloat16(h - __bfloat162float(hh));
        }
        __syncthreads();
        if (tid < 128) {
            const float4 v = make_float4(hstg[0 * 128 + tid], hstg[1 * 128 + tid],
                                         hstg[2 * 128 + tid], hstg[3 * 128 + tid]);
            *(float4*)(out + ((size_t)t * BATCH + tid) * HID + j0) = v;
        }
        __threadfence();
        grid_barrier(128);
    }

    // final h, c
    {
        const size_t oh = (size_t)TSTEPS * BATCH * HID;
#pragma unroll
        for (int q = 0; q < 2; q++) {
            const int u = ug + q;
            out[oh + (size_t)b_ * HID + j0 + u]                       = hreg[q];
            out[oh + (size_t)BATCH * HID + (size_t)b_ * HID + j0 + u] = creg[q];
        }
    }
}

// ---------------------------------------------------------------------------
extern "C" void kernel_launch(void* const* d_in, const int* in_sizes, int n_in,
                              void* d_out, int out_size) {
    const float* x   = (const float*)d_in[0];
    const float* Wih = (const float*)d_in[1];
    const float* bih = (const float*)d_in[2];
    const float* Whh = (const float*)d_in[3];
    const float* bhh = (const float*)d_in[4];
    float* out = (float*)d_out;
    (void)in_sizes; (void)n_in; (void)out_size;

    split_x_kernel<<<4096, 256>>>(x);
    split_w_kernel<<<512, 256>>>(Wih);

    cudaFuncSetAttribute(xproj_mma_kernel,
                         cudaFuncAttributeMaxDynamicSharedMemorySize, SMEM_XP);
    dim3 g1(GATES / 128, TSTEPS);
    xproj_mma_kernel<<<g1, 256, SMEM_XP>>>(bih, bhh);

    cudaFuncSetAttribute(rec3_kernel,
                         cudaFuncAttributeMaxDynamicSharedMemorySize, SMEM_REC3);
    rec3_kernel<<<128, 256, SMEM_REC3>>>(Whh, out);
}